// round 1
// baseline (speedup 1.0000x reference)
#include <cuda_runtime.h>

// ARIMA(2,1,2) epsilon recursion, B=1024 rows, L=65536.
// eps_t = y[t+3] - (1+phi0)*y[t+2] - phi1*y[t+1] - mu - th0*eps_{t-1} - th1*eps_{t-2}
// Chunked-parallel with 64-step warm-up (IIR state decays geometrically).
// Fully coalesced global I/O via shared-memory staging.

#define B_ROWS  1024
#define L_LEN   65536
#define N_OUT   65535
#define N_EPS   65533
#define BTH     256
#define CPR     74          // chunks per row  (74*896 = 66304 >= 65533)
#define CSZ     896         // outputs per chunk (28 tiles)
#define WUP     64          // warm-up steps (2 tiles)
#define TT      32          // steps per tile
#define NTILES  30          // (WUP+CSZ)/TT
#define PAD     33          // smem row stride (conflict-free)
#define GRID    296         // 1024*74/256  == 2 blocks per SM

__global__ __launch_bounds__(BTH, 2)
void arima_eps_kernel(const float* __restrict__ y,
                      const float* __restrict__ phi,
                      const float* __restrict__ theta,
                      const float* __restrict__ mu,
                      float* __restrict__ out)
{
    extern __shared__ float smem[];
    float* buf0 = smem;                       // window buffers [256][PAD]
    float* buf1 = smem + BTH * PAD;
    int4*  sm_p = (int4*)(smem + 2 * BTH * PAD);  // .x=ybase .y=startT .z=obase

    const int tid  = threadIdx.x;
    const int w    = tid >> 5;
    const int lane = tid & 31;

    const float phi0 = phi[0];
    const float phi1 = phi[1];
    const float th0  = theta[0];
    const float th1  = theta[1];
    const float muv  = mu[0];
    const float c2   = 1.0f + phi0;

    // Per-segment (=per-thread chunk) parameters, shared so any thread can
    // address any segment during the cooperative load/store stages.
    {
        int cid = blockIdx.x * BTH + tid;
        int row = cid / CPR;
        int cno = cid - row * CPR;
        int4 p;
        p.x = row * L_LEN;          // y row base
        p.y = cno * CSZ - WUP;      // startT (first step index incl. warm-up)
        p.z = row * N_OUT;          // out row base
        p.w = 0;
        sm_p[tid] = p;
    }
    __syncthreads();

    // Cooperative, coalesced load of window m (y[startT + m*32 .. +31], clamped)
    // for all 256 segments. Warp handles one 128B segment per iteration.
    auto load_window = [&](int m, float* dst) {
        #pragma unroll
        for (int j = 0; j < 32; ++j) {
            int s = j * 8 + w;                  // warp-uniform segment index
            int4 p = sm_p[s];
            int pos = p.y + m * TT + lane;
            pos = (pos < 0) ? 0 : pos;
            pos = (pos > L_LEN - 1) ? (L_LEN - 1) : pos;
            dst[s * PAD + lane] = y[p.x + pos];
        }
    };

    load_window(0, buf0);
    load_window(1, buf1);
    __syncthreads();

    const int myStart = sm_p[tid].y;
    // carries: yc1 = y[t+1], yc2 = y[t+2] for the upcoming step t
    float yc1 = buf0[tid * PAD + 1];
    float yc2 = buf0[tid * PAD + 2];
    float e1 = 0.f, e2 = 0.f;

    float* bufs[2] = {buf0, buf1};

    for (int k = 0; k < NTILES; ++k) {
        float* bA = bufs[k & 1] + tid * PAD;        // window k   (own row)
        float* bB = bufs[(k + 1) & 1] + tid * PAD;  // window k+1 (own row)
        int tbase = myStart + k * TT;
        // chunk 0 has no real warm-up: reset state exactly at t=0
        if (tbase == 0) { e1 = 0.f; e2 = 0.f; }

        #pragma unroll
        for (int e = 0; e < TT; ++e) {
            float ynew = (e <= 28) ? bA[e + 3] : bB[e - 29];   // y[t+3]
            float a = ynew - c2 * yc2;
            a = a - phi1 * yc1;
            a = a - muv;
            float epsv = a - th0 * e1;
            epsv = epsv - th1 * e2;
            e2 = e1; e1 = epsv;
            bA[e] = epsv;               // in-place: slot e already consumed
            yc1 = yc2; yc2 = ynew;
        }
        __syncthreads();

        // Cooperative, coalesced store of output tiles (skip warm-up tiles)
        if (k >= WUP / TT) {
            float* src = bufs[k & 1];
            #pragma unroll
            for (int j = 0; j < 32; ++j) {
                int s = j * 8 + w;
                int4 p = sm_p[s];
                int t = p.y + k * TT + lane;
                if (t < N_OUT) {
                    float v = (t < N_EPS) ? src[s * PAD + lane] : 0.0f;
                    out[p.z + t] = v;
                }
            }
        }
        __syncthreads();

        if (k + 2 <= NTILES) {
            load_window(k + 2, bufs[k & 1]);    // prefetch next-next window
        }
        __syncthreads();
    }
}

extern "C" void kernel_launch(void* const* d_in, const int* in_sizes, int n_in,
                              void* d_out, int out_size) {
    const float* y     = (const float*)d_in[0];
    const float* phi   = (const float*)d_in[1];
    const float* theta = (const float*)d_in[2];
    const float* mu    = (const float*)d_in[3];
    float* out = (float*)d_out;

    size_t smem_bytes = 2 * BTH * PAD * sizeof(float) + BTH * sizeof(int4);
    cudaFuncSetAttribute(arima_eps_kernel,
                         cudaFuncAttributeMaxDynamicSharedMemorySize,
                         (int)smem_bytes);
    arima_eps_kernel<<<GRID, BTH, smem_bytes>>>(y, phi, theta, mu, out);
}

// round 3
// speedup vs baseline: 4.3342x; 4.3342x over previous
#include <cuda_runtime.h>
#include <cstdint>

// ARIMA(2,1,2) eps recursion, B=1024, L=65536.
// eps_t = y[t+3] - (1+phi0)*y[t+2] - phi1*y[t+1] - mu - th0*eps_{t-1} - th1*eps_{t-2}
// Chunk-parallel (74 chunks/row, 64-step warm-up, IIR state decays ~rho^64).
// 3-stage cp.async ring, XOR-swizzled smem, LDS.128/STS.128, coalesced STG.

#define L_LEN   65536
#define N_OUT   65535
#define N_EPS   65533
#define BTH     512
#define NWARP   16
#define CPR     74           // chunks per row (74*896 >= 65533)
#define CSZ     896          // outputs per chunk
#define WUP     64           // warm-up steps (2 tiles)
#define TT      32           // steps per tile
#define NTILES  30           // (WUP+CSZ)/TT
#define NSTG    3            // cp.async ring stages
#define STAGE_F4 (BTH*8)     // float4 per stage (64KB)
#define GRID    148          // 1024*74 / 512 == one block per SM

__device__ __forceinline__ uint32_t smem_u32(const void* p) {
    uint32_t a;
    asm("{ .reg .u64 t; cvta.to.shared.u64 t, %1; cvt.u32.u64 %0, t; }"
        : "=r"(a) : "l"(p));
    return a;
}

__global__ __launch_bounds__(BTH, 1)
void arima_eps_kernel(const float* __restrict__ y,
                      const float* __restrict__ phi,
                      const float* __restrict__ theta,
                      const float* __restrict__ mu,
                      float* __restrict__ out)
{
    extern __shared__ float smem[];              // 3 stages + segment table
    float4* stg  = (float4*)smem;                // [NSTG][BTH][8] float4, swizzled
    int4*   sm_p = (int4*)(smem + NSTG * STAGE_F4 * 4);

    const int tid  = threadIdx.x;
    const int w    = tid >> 5;
    const int lane = tid & 31;

    const float phi0 = phi[0];
    const float phi1 = phi[1];
    const float th0  = theta[0];
    const float th1  = theta[1];
    const float muv  = mu[0];
    const float c2   = 1.0f + phi0;

    // Per-segment params: .x = y row base, .y = startT (incl. warm-up), .z = out base
    {
        int cid = blockIdx.x * BTH + tid;
        int row = cid / CPR;
        int cno = cid - row * CPR;
        int4 p;
        p.x = row * L_LEN;
        p.y = cno * CSZ - WUP;
        p.z = row * N_OUT;
        p.w = 0;
        sm_p[tid] = p;
    }
    __syncthreads();

    const uint32_t smem0 = smem_u32(smem);

    // Issue one 64KB window (512 segments x 32 floats) via 16B cp.async.
    // Out-of-range chunks (warm-up before t=0, tail past L) are zero-filled;
    // both only feed forgotten warm-up state or masked outputs.
    auto issue_window = [&](int m, int stage) {
        uint32_t sbase = smem0 + (uint32_t)stage * (STAGE_F4 * 16);
        #pragma unroll
        for (int it = 0; it < 8; ++it) {
            int s = it * 64 + (tid >> 3);
            int c = tid & 7;
            int4 p = sm_p[s];
            int pos = p.y + m * TT + c * 4;
            bool ok = (pos >= 0) && (pos <= L_LEN - 4);
            int cpos = pos < 0 ? 0 : (pos > L_LEN - 4 ? L_LEN - 4 : pos);
            const float* src = y + p.x + cpos;
            uint32_t dst = sbase + (uint32_t)(s * 128 + ((c ^ (s & 7)) << 4));
            int n = ok ? 16 : 0;
            asm volatile("cp.async.cg.shared.global [%0], [%1], 16, %2;\n"
                         :: "r"(dst), "l"(src), "r"(n));
        }
        asm volatile("cp.async.commit_group;\n" ::: "memory");
    };

    issue_window(0, 0);
    issue_window(1, 1);
    issue_window(2, 2);

    const int myStart = sm_p[tid].y;
    float e1 = 0.f, e2 = 0.f, yc1 = 0.f, yc2 = 0.f;

    for (int k = 0; k < NTILES; ++k) {
        // windows k and k+1 must be resident (peek reads 3 floats of k+1)
        asm volatile("cp.async.wait_group 1;\n" ::: "memory");
        __syncthreads();

        const int stA = k % NSTG;
        const int stB = (k + 1) % NSTG;

        // v[0..31] = y[base .. base+31], v[32..34] from next window (peek)
        float v[35];
        {
            float4* ra = stg + stA * STAGE_F4 + tid * 8;
            #pragma unroll
            for (int c = 0; c < 8; ++c) {
                float4 q = ra[c ^ (tid & 7)];
                v[c*4+0] = q.x; v[c*4+1] = q.y; v[c*4+2] = q.z; v[c*4+3] = q.w;
            }
            float4 pk = (stg + stB * STAGE_F4 + tid * 8)[tid & 7];  // chunk 0
            v[32] = pk.x; v[33] = pk.y; v[34] = pk.z;
        }

        const int tbase = myStart + k * TT;
        if (tbase == 0) { e1 = 0.f; e2 = 0.f; }   // exact state reset at t=0

        #pragma unroll
        for (int e = 0; e < TT; ++e) {
            float ynew = v[e + 3];                 // y[t+3]
            float a = ynew - c2 * yc2;
            a = fmaf(-phi1, yc1, a) - muv;         // independent of eps chain
            float ep = fmaf(-th0, e1, a);
            ep = fmaf(-th1, e2, ep);               // 2-FMA dependent chain
            e2 = e1; e1 = ep;
            yc1 = yc2; yc2 = ynew;
            v[e] = ep;                             // v[e] consumed at step e-3
        }

        // eps back to stage A (same swizzled layout), 8x STS.128
        {
            float4* ra = stg + stA * STAGE_F4 + tid * 8;
            #pragma unroll
            for (int c = 0; c < 8; ++c) {
                ra[c ^ (tid & 7)] =
                    make_float4(v[c*4+0], v[c*4+1], v[c*4+2], v[c*4+3]);
            }
        }
        __syncthreads();

        // Cooperative coalesced store (skip warm-up tiles k<2).
        if (k >= WUP / TT) {
            const float* sf = smem + stA * STAGE_F4 * 4;
            #pragma unroll
            for (int j = 0; j < 32; ++j) {
                int s = j * NWARP + w;             // warp-uniform segment
                int4 p = sm_p[s];
                int t = p.y + k * TT + lane;
                if (t < N_OUT) {
                    int word = s * 32 + (((lane >> 2) ^ (s & 7)) << 2) + (lane & 3);
                    out[p.z + t] = (t < N_EPS) ? sf[word] : 0.0f;
                }
            }
        }
        __syncthreads();

        // Refill freed stage. Windows 0..NTILES are needed (tile k peeks into
        // window k+1), so issue while m = k+NSTG <= NTILES. Otherwise commit
        // an empty group to keep wait_group accounting uniform.
        if (k + NSTG <= NTILES) {
            issue_window(k + NSTG, stA);
        } else {
            asm volatile("cp.async.commit_group;\n" ::: "memory");
        }
    }
}

extern "C" void kernel_launch(void* const* d_in, const int* in_sizes, int n_in,
                              void* d_out, int out_size) {
    const float* y     = (const float*)d_in[0];
    const float* phi   = (const float*)d_in[1];
    const float* theta = (const float*)d_in[2];
    const float* mu    = (const float*)d_in[3];
    float* out = (float*)d_out;

    size_t smem_bytes = (size_t)NSTG * STAGE_F4 * 16 + BTH * sizeof(int4);
    cudaFuncSetAttribute(arima_eps_kernel,
                         cudaFuncAttributeMaxDynamicSharedMemorySize,
                         (int)smem_bytes);
    arima_eps_kernel<<<GRID, BTH, smem_bytes>>>(y, phi, theta, mu, out);
}